// round 16
// baseline (speedup 1.0000x reference)
#include <cuda_runtime.h>
#include <cuda_fp16.h>

#define S_LEN 4096
#define TWO_PI_F 6.28318530717958647692f

typedef unsigned long long u64;

// Pair-packed fp16 weights: index (jp*64 + i2), jp = j/2, i2 = i-pair.
//   .x = half2( W[2i2][2jp],   W[2i2+1][2jp]   )
//   .y = half2( W[2i2][2jp+1], W[2i2+1][2jp+1] )
__device__ float  g_cPt[64 * 64];     // fp32 [j][i]
__device__ float  g_rpVt[64 * 64];    // [j][i] = 1/(i*64+j+2)
__device__ uint2  g_M1p[32 * 64];
__device__ uint2  g_R1p[32 * 64];
__device__ uint2  g_M2p[64 * 64];
__device__ uint2  g_P1p[64 * 64];
__device__ uint2  g_P2p[64 * 64];
// build rp: per (jp,i2): ( rp(i0,j), rp(i1,j), rp(i0,j+1), rp(i1,j+1) )
__device__ float4 g_rpP[64 * 64];

__device__ __forceinline__ unsigned packh2(float lo, float hi)
{
    __half2 h = __floats2half2_rn(lo, hi);
    return *(unsigned*)&h;
}

__global__ void prep_kernel(
    const float* __restrict__ cP, const float* __restrict__ M1,
    const float* __restrict__ R1, const float* __restrict__ M2,
    const float* __restrict__ P1, const float* __restrict__ P2)
{
    int t = blockIdx.x * blockDim.x + threadIdx.x;
    if (t < 4096) {                       // D mats: jp<64, i2<64
        int jp = t >> 6, i2l = t & 63;
        int j = 2 * jp, i0 = 2 * i2l, i1 = i0 + 1;
        uint2 v;
        v.x = packh2(M2[i0*128 + j],     M2[i1*128 + j]);
        v.y = packh2(M2[i0*128 + j + 1], M2[i1*128 + j + 1]);
        g_M2p[t] = v;
        v.x = packh2(P1[i0*128 + j],     P1[i1*128 + j]);
        v.y = packh2(P1[i0*128 + j + 1], P1[i1*128 + j + 1]);
        g_P1p[t] = v;
        v.x = packh2(P2[i0*128 + j],     P2[i1*128 + j]);
        v.y = packh2(P2[i0*128 + j + 1], P2[i1*128 + j + 1]);
        g_P2p[t] = v;
        float4 r;
        r.x = 1.0f / (float)(i0*128 + j + 2);
        r.y = 1.0f / (float)(i1*128 + j + 2);
        r.z = 1.0f / (float)(i0*128 + j + 3);
        r.w = 1.0f / (float)(i1*128 + j + 3);
        g_rpP[t] = r;
    }
    if (t < 2048) {                       // V mats: jp<32, i2<64
        int jp = t >> 6, i2l = t & 63;
        int j = 2 * jp, i0 = 2 * i2l, i1 = i0 + 1;
        uint2 v;
        v.x = packh2(M1[i0*64 + j],     M1[i1*64 + j]);
        v.y = packh2(M1[i0*64 + j + 1], M1[i1*64 + j + 1]);
        g_M1p[t] = v;
        v.x = packh2(R1[i0*64 + j],     R1[i1*64 + j]);
        v.y = packh2(R1[i0*64 + j + 1], R1[i1*64 + j + 1]);
        g_R1p[t] = v;
    }
    if (t < 4096) {
        int i = t >> 6, j = t & 63;
        g_cPt[j * 64 + i] = cP[t];
        g_rpVt[t] = 1.0f / (float)((t & 63) * 64 + (t >> 6) + 2);
    }
}

__device__ __forceinline__ float pcos(float sf, float rp)
{
    float f = sf * rp;
    float n = rintf(f);
    float r = fmaf(sf, rp, -n);
    return __cosf(TWO_PI_F * r);
}

// ---- packed f32x2 helpers; payload in u64 ----
__device__ __forceinline__ u64 fma2(u64 a, u64 b, u64 c)
{ u64 d; asm("fma.rn.f32x2 %0, %1, %2, %3;" : "=l"(d) : "l"(a), "l"(b), "l"(c)); return d; }
__device__ __forceinline__ u64 mul2(u64 a, u64 b)
{ u64 d; asm("mul.rn.f32x2 %0, %1, %2;" : "=l"(d) : "l"(a), "l"(b)); return d; }
__device__ __forceinline__ u64 add2(u64 a, u64 b)
{ u64 d; asm("add.rn.f32x2 %0, %1, %2;" : "=l"(d) : "l"(a), "l"(b)); return d; }
__device__ __forceinline__ u64 bcast2(float x)
{ u64 d; asm("mov.b64 %0, {%1, %1};" : "=l"(d) : "f"(x)); return d; }
__device__ __forceinline__ u64 f2d(float x, float y)
{ u64 d; asm("mov.b64 %0, {%1, %2};" : "=l"(d) : "f"(x), "f"(y)); return d; }
__device__ __forceinline__ float2 d2f(u64 d)
{ float2 v; asm("mov.b64 {%0, %1}, %2;" : "=f"(v.x), "=f"(v.y) : "l"(d)); return v; }

// smem layout (float units)
#define OFF_PHI  0          // 4096 uint2 = 8192 floats
#define OFF_PART 8192       // 2048 u64 = 4096 floats
#define OFF_XST  12288      // 256
#define OFF_HST  12544      // 256
#define OFF_LN1  12800      // 512
#define OFF_H1S  13312      // 512
#define OFF_LN2  13824      // 512
#define OFF_WSMU 14336      // 16 u64 = 32 floats
#define OFF_WSQU 14368      // 32
#define SM_FLOATS 14400
#define SMEM_BYTES (SM_FLOATS * 4)

#define DECL_ACC u64 A00 = 0, A01 = 0, A10 = 0, A11 = 0;

// FMA body for one j-pair; acts fetched from lane-resident actR via shuffle
#define PAIR_BODY_SH(JPL) {                                             \
    u64 aAx = __shfl_sync(0xffffffffu, actR, 4*(JPL));                  \
    u64 aAy = __shfl_sync(0xffffffffu, actR, 4*(JPL)+1);                \
    u64 aBx = __shfl_sync(0xffffffffu, actR, 4*(JPL)+2);                \
    u64 aBy = __shfl_sync(0xffffffffu, actR, 4*(JPL)+3);                \
    u64 w0 = bcast2(wa.x), w1 = bcast2(wa.y);                           \
    A00 = fma2(w0, aAx, A00); A01 = fma2(w0, aAy, A01);                 \
    A10 = fma2(w1, aAx, A10); A11 = fma2(w1, aAy, A11);                 \
    w0 = bcast2(wb.x); w1 = bcast2(wb.y);                               \
    A00 = fma2(w0, aBx, A00); A01 = fma2(w0, aBy, A01);                 \
    A10 = fma2(w1, aBx, A10); A11 = fma2(w1, aBy, A11); }

#define WPAIR_SH(WP_, JP, JPL) {                                        \
    uint2 wu = WP_[(JP) * 64 + i2];                                     \
    float2 wa = __half22float2(*(__half2*)&wu.x);                       \
    float2 wb = __half22float2(*(__half2*)&wu.y);                       \
    PAIR_BODY_SH(JPL) }

#define PPAIR_SH(WP_, JP, JPL) {                                        \
    uint2 wu = WP_[(JP) * 64 + i2];                                     \
    uint2 pu = phiP[(JP) * 64 + i2];                                    \
    __half2 m0 = __hmul2(*(__half2*)&wu.x, *(__half2*)&pu.x);           \
    __half2 m1 = __hmul2(*(__half2*)&wu.y, *(__half2*)&pu.y);           \
    float2 wa = __half22float2(m0);                                     \
    float2 wb = __half22float2(m1);                                     \
    PAIR_BODY_SH(JPL) }

// partials: [slice][c][i2] u64, c = (i&1)*2 + batch-pair
#define STOREP() {                                                      \
    partd[js8 * 256 +   0 + i2] = A00;                                  \
    partd[js8 * 256 +  64 + i2] = A01;                                  \
    partd[js8 * 256 + 128 + i2] = A10;                                  \
    partd[js8 * 256 + 192 + i2] = A11; }

__global__ __launch_bounds__(512, 2)
void hier_kernel(const int*   __restrict__ tokens,
                 const int*   __restrict__ positions,
                 const float* __restrict__ emb,
                 const float* __restrict__ g1, const float* __restrict__ b1,
                 const float* __restrict__ g2, const float* __restrict__ b2,
                 float*       __restrict__ out)
{
    extern __shared__ __align__(16) float sm[];
    uint2* phiP  = (uint2*)(sm + OFF_PHI);      // [jp*64 + i2]
    u64*   partd = (u64*)(sm + OFF_PART);
    float* xsT   = sm + OFF_XST;                // [j][4b]
    float* hsT   = sm + OFF_HST;
    float* ln1T  = sm + OFF_LN1;
    float* h1sT  = sm + OFF_H1S;
    float* ln2T  = sm + OFF_LN2;
    u64*   wsmU  = (u64*)(sm + OFF_WSMU);
    u64*   wsqU  = (u64*)(sm + OFF_WSQU);

    const int tid = threadIdx.x;
    const int s   = blockIdx.x;
    const float sf = (float)positions[s];

    // ---- build pair-packed fp16 phiD: 4096 uint2 over 512 threads ----
#pragma unroll
    for (int m = 0; m < 8; ++m) {
        int idx = m * 512 + tid;
        float4 rp = g_rpP[idx];
        uint2 pk;
        pk.x = packh2(pcos(sf, rp.x), pcos(sf, rp.y));
        pk.y = packh2(pcos(sf, rp.z), pcos(sf, rp.w));
        phiP[idx] = pk;
    }

    // ---- gather embeddings: xsT[j][b] ----
    if (tid < 256) {
        int b0 = tid >> 6, j0 = tid & 63;
        int tok = tokens[b0 * S_LEN + s];
        xsT[j0 * 4 + b0] = emb[tok * 64 + j0];
    }
    __syncthreads();

    // =====================================================================
    // Layer 0 (V=64): 64 i x 8 j-slices of 8; acts via shuffle
    // =====================================================================
    {
        const int i = tid & 63, sl = tid >> 6;
        u64 actR = ((const u64*)xsT)[sl * 16 + (tid & 15)];
        u64 a01 = 0, a23 = 0;
#pragma unroll
        for (int jj = 0; jj < 8; ++jj) {
            int j = sl * 8 + jj;
            float pw = g_cPt[j * 64 + i] * pcos(sf, g_rpVt[j * 64 + i]);
            u64 p2 = bcast2(pw);
            u64 ax = __shfl_sync(0xffffffffu, actR, 2 * jj);
            u64 ay = __shfl_sync(0xffffffffu, actR, 2 * jj + 1);
            a01 = fma2(p2, ax, a01);
            a23 = fma2(p2, ay, a23);
        }
        ulonglong2 st; st.x = a01; st.y = a23;
        *(ulonglong2*)&partd[sl * 128 + i * 2] = st;
    }
    __syncthreads();
    if (tid < 128) {
        u64 v = 0;
#pragma unroll
        for (int sl = 0; sl < 8; ++sl) v = add2(v, partd[sl * 128 + tid]);
        *(u64*)&hsT[tid * 2] = v;   // hsT[i][4b]
    }
    __syncthreads();

    // D-stage mapping: warp = (i-half, j-slice)
    const int w   = tid >> 5;
    const int js8 = w >> 1;                    // 0..7
    const int i2  = (w & 1) * 32 + (tid & 31); // i-pair 0..63
    // reduce mapping (tid<256): c = tid>>6 (ih*2+bp), i2r = tid&63
    const int rc  = tid >> 6;
    const int rbp = rc & 1;
    const int rii = 2 * (tid & 63) + (rc >> 1);

    // =====================================================================
    // t1 = M1 @ h : jp<32, 4 per slice
    // =====================================================================
    {
        DECL_ACC;
        u64 actR = ((const u64*)hsT)[js8 * 16 + (tid & 15)];
        const int jp0 = js8 * 4;
        WPAIR_SH(g_M1p, jp0 + 0, 0); WPAIR_SH(g_M1p, jp0 + 1, 1);
        WPAIR_SH(g_M1p, jp0 + 2, 2); WPAIR_SH(g_M1p, jp0 + 3, 3);
        STOREP();
    }
    __syncthreads();

    // ---- reduce t1 + LayerNorm 1 (value kept in register across sync) ----
    u64 vKeep = 0;
    if (tid < 256) {
        u64 v = 0;
#pragma unroll
        for (int sl = 0; sl < 8; ++sl) v = add2(v, partd[sl * 256 + tid]);
        vKeep = v;
        u64 sv = v, sq = mul2(v, v);
#pragma unroll
        for (int o = 1; o <= 16; o <<= 1) {
            sv = add2(sv, __shfl_xor_sync(0xffffffffu, sv, o));
            sq = add2(sq, __shfl_xor_sync(0xffffffffu, sq, o));
        }
        if ((tid & 31) == 0) { wsmU[tid >> 5] = sv; wsqU[tid >> 5] = sq; }
    }
    __syncthreads();
    if (tid < 256) {
        u64 smS = add2(add2(wsmU[rbp * 2], wsmU[rbp * 2 + 1]),
                       add2(wsmU[rbp * 2 + 4], wsmU[rbp * 2 + 5]));
        u64 sqS = add2(add2(wsqU[rbp * 2], wsqU[rbp * 2 + 1]),
                       add2(wsqU[rbp * 2 + 4], wsqU[rbp * 2 + 5]));
        u64 mean2 = mul2(smS, bcast2(0.0078125f));
        u64 ex2   = mul2(sqS, bcast2(0.0078125f));
        u64 nm    = mul2(mean2, bcast2(-1.f));
        u64 var2  = fma2(mean2, nm, ex2);
        float2 vf = d2f(add2(var2, bcast2(1e-5f)));
        u64 rstd2 = f2d(rsqrtf(vf.x), rsqrtf(vf.y));
        u64 cen   = add2(vKeep, nm);
        *(u64*)&ln1T[rii * 4 + rbp * 2] =
            fma2(bcast2(g1[rii]), mul2(cen, rstd2), bcast2(b1[rii]));
    }
    __syncthreads();

    // =====================================================================
    // h1 = posnk(ln1, P1, phi) + R1 @ h : 8 P-jp + 4 R-jp per slice
    // =====================================================================
    {
        DECL_ACC;
        {
            u64 actR = ((const u64*)ln1T)[js8 * 32 + (tid & 31)];
            const int jp0 = js8 * 8;
            PPAIR_SH(g_P1p, jp0 + 0, 0); PPAIR_SH(g_P1p, jp0 + 1, 1);
            PPAIR_SH(g_P1p, jp0 + 2, 2); PPAIR_SH(g_P1p, jp0 + 3, 3);
            PPAIR_SH(g_P1p, jp0 + 4, 4); PPAIR_SH(g_P1p, jp0 + 5, 5);
            PPAIR_SH(g_P1p, jp0 + 6, 6); PPAIR_SH(g_P1p, jp0 + 7, 7);
        }
        {
            u64 actR = ((const u64*)hsT)[js8 * 16 + (tid & 15)];
            const int jr0 = js8 * 4;
            WPAIR_SH(g_R1p, jr0 + 0, 0); WPAIR_SH(g_R1p, jr0 + 1, 1);
            WPAIR_SH(g_R1p, jr0 + 2, 2); WPAIR_SH(g_R1p, jr0 + 3, 3);
        }
        STOREP();
    }
    __syncthreads();
    if (tid < 256) {
        u64 v = 0;
#pragma unroll
        for (int sl = 0; sl < 8; ++sl) v = add2(v, partd[sl * 256 + tid]);
        *(u64*)&h1sT[rii * 4 + rbp * 2] = v;
    }
    __syncthreads();

    // =====================================================================
    // t2 = M2 @ h1 : 8 jp per slice
    // =====================================================================
    {
        DECL_ACC;
        u64 actR = ((const u64*)h1sT)[js8 * 32 + (tid & 31)];
        const int jp0 = js8 * 8;
        WPAIR_SH(g_M2p, jp0 + 0, 0); WPAIR_SH(g_M2p, jp0 + 1, 1);
        WPAIR_SH(g_M2p, jp0 + 2, 2); WPAIR_SH(g_M2p, jp0 + 3, 3);
        WPAIR_SH(g_M2p, jp0 + 4, 4); WPAIR_SH(g_M2p, jp0 + 5, 5);
        WPAIR_SH(g_M2p, jp0 + 6, 6); WPAIR_SH(g_M2p, jp0 + 7, 7);
        STOREP();
    }
    __syncthreads();

    // ---- reduce t2 + LayerNorm 2 (t2d kept in register for residual) ----
    u64 t2d = 0;
    if (tid < 256) {
#pragma unroll
        for (int sl = 0; sl < 8; ++sl) t2d = add2(t2d, partd[sl * 256 + tid]);
        u64 sv = t2d, sq = mul2(t2d, t2d);
#pragma unroll
        for (int o = 1; o <= 16; o <<= 1) {
            sv = add2(sv, __shfl_xor_sync(0xffffffffu, sv, o));
            sq = add2(sq, __shfl_xor_sync(0xffffffffu, sq, o));
        }
        if ((tid & 31) == 0) { wsmU[tid >> 5] = sv; wsqU[tid >> 5] = sq; }
    }
    __syncthreads();
    if (tid < 256) {
        u64 smS = add2(add2(wsmU[rbp * 2], wsmU[rbp * 2 + 1]),
                       add2(wsmU[rbp * 2 + 4], wsmU[rbp * 2 + 5]));
        u64 sqS = add2(add2(wsqU[rbp * 2], wsqU[rbp * 2 + 1]),
                       add2(wsqU[rbp * 2 + 4], wsqU[rbp * 2 + 5]));
        u64 mean2 = mul2(smS, bcast2(0.0078125f));
        u64 ex2   = mul2(sqS, bcast2(0.0078125f));
        u64 nm    = mul2(mean2, bcast2(-1.f));
        u64 var2  = fma2(mean2, nm, ex2);
        float2 vf = d2f(add2(var2, bcast2(1e-5f)));
        u64 rstd2 = f2d(rsqrtf(vf.x), rsqrtf(vf.y));
        u64 cen   = add2(t2d, nm);
        *(u64*)&ln2T[rii * 4 + rbp * 2] =
            fma2(bcast2(g2[rii]), mul2(cen, rstd2), bcast2(b2[rii]));
    }
    __syncthreads();

    // =====================================================================
    // out = posnk(ln2, P2, phi) + t2
    // =====================================================================
    {
        DECL_ACC;
        u64 actR = ((const u64*)ln2T)[js8 * 32 + (tid & 31)];
        const int jp0 = js8 * 8;
        PPAIR_SH(g_P2p, jp0 + 0, 0); PPAIR_SH(g_P2p, jp0 + 1, 1);
        PPAIR_SH(g_P2p, jp0 + 2, 2); PPAIR_SH(g_P2p, jp0 + 3, 3);
        PPAIR_SH(g_P2p, jp0 + 4, 4); PPAIR_SH(g_P2p, jp0 + 5, 5);
        PPAIR_SH(g_P2p, jp0 + 6, 6); PPAIR_SH(g_P2p, jp0 + 7, 7);
        STOREP();
    }
    __syncthreads();
    if (tid < 256) {
        u64 v = t2d;
#pragma unroll
        for (int sl = 0; sl < 8; ++sl) v = add2(v, partd[sl * 256 + tid]);
        float2 f = d2f(v);
        out[((size_t)(2 * rbp)     * S_LEN + s) * 128 + rii] = f.x;
        out[((size_t)(2 * rbp + 1) * S_LEN + s) * 128 + rii] = f.y;
    }
}

extern "C" void kernel_launch(void* const* d_in, const int* in_sizes, int n_in,
                              void* d_out, int out_size)
{
    const int*   tokens    = (const int*)  d_in[0];
    const int*   positions = (const int*)  d_in[1];
    const float* emb       = (const float*)d_in[2];
    const float* char_P    = (const float*)d_in[3];
    const float* M1        = (const float*)d_in[4];
    const float* P1        = (const float*)d_in[5];
    const float* g1        = (const float*)d_in[6];
    const float* b1        = (const float*)d_in[7];
    const float* R1        = (const float*)d_in[8];
    const float* M2        = (const float*)d_in[9];
    const float* P2        = (const float*)d_in[10];
    const float* g2        = (const float*)d_in[11];
    const float* b2        = (const float*)d_in[12];
    float* out = (float*)d_out;

    cudaFuncSetAttribute(hier_kernel,
                         cudaFuncAttributeMaxDynamicSharedMemorySize, SMEM_BYTES);

    prep_kernel<<<32, 512>>>(char_P, M1, R1, M2, P1, P2);
    hier_kernel<<<S_LEN, 512, SMEM_BYTES>>>(tokens, positions, emb,
                                            g1, b1, g2, b2, out);
}